// round 1
// baseline (speedup 1.0000x reference)
#include <cuda_runtime.h>
#include <cstdint>

#define BB 16
#define NN 2048
#define DD 256
#define EPSF 1e-9f

// ---------------- scratch (static __device__ globals; no allocation) --------
__device__ float g_pw[(size_t)BB * NN * NN];   // 268 MB pairwise distances
__device__ float g_pn[BB * NN];                // |preds|^2 per row
__device__ float g_ln[BB * NN];                // |labels|^2 per row
__device__ float g_S[BB * NN];                 // row sums of e
__device__ float g_T[BB * NN];                 // col sums of b
__device__ float g_W[BB * NN];                 // col sums of b*pw
__device__ float g_cost[2][BB * NN];           // ping-pong cost
__device__ float g_curr[BB * NN];              // currency
__device__ float g_bw[BB * NN];                // bid weights

// ---------------- reductions ------------------------------------------------
__device__ __forceinline__ float block_reduce_sum(float v) {
    __shared__ float red[8];
    int lane = threadIdx.x & 31, warp = threadIdx.x >> 5;
#pragma unroll
    for (int o = 16; o; o >>= 1) v += __shfl_down_sync(0xffffffffu, v, o);
    if (lane == 0) red[warp] = v;
    __syncthreads();
    if (warp == 0) {
        v = (lane < 8) ? red[lane] : 0.f;
#pragma unroll
        for (int o = 4; o; o >>= 1) v += __shfl_down_sync(0xffffffffu, v, o);
    }
    return v;  // valid in thread 0
}

__device__ __forceinline__ void block_reduce_sum2(float& a, float& b) {
    __shared__ float reda[8], redb[8];
    int lane = threadIdx.x & 31, warp = threadIdx.x >> 5;
#pragma unroll
    for (int o = 16; o; o >>= 1) {
        a += __shfl_down_sync(0xffffffffu, a, o);
        b += __shfl_down_sync(0xffffffffu, b, o);
    }
    if (lane == 0) { reda[warp] = a; redb[warp] = b; }
    __syncthreads();
    if (warp == 0) {
        a = (lane < 8) ? reda[lane] : 0.f;
        b = (lane < 8) ? redb[lane] : 0.f;
#pragma unroll
        for (int o = 4; o; o >>= 1) {
            a += __shfl_down_sync(0xffffffffu, a, o);
            b += __shfl_down_sync(0xffffffffu, b, o);
        }
    }
}

// ---------------- init ------------------------------------------------------
__global__ void init_kernel(float* out) {
    int i = blockIdx.x * blockDim.x + threadIdx.x;
    if (i < BB * NN) {
        g_cost[0][i] = 1.f;
        g_curr[i] = 1.f;
        g_T[i] = 0.f;
        g_W[i] = 0.f;
    }
    if (i == 0) out[0] = 0.f;
}

// ---------------- squared norms (warp per row of 256) ----------------------
__global__ __launch_bounds__(256) void norms_kernel(const float* __restrict__ P,
                                                    const float* __restrict__ L) {
    int warp = (blockIdx.x * blockDim.x + threadIdx.x) >> 5;
    int lane = threadIdx.x & 31;
    if (warp >= 2 * BB * NN) return;
    const float* src;
    float* dst;
    int r;
    if (warp < BB * NN) { src = P; dst = g_pn; r = warp; }
    else                { src = L; dst = g_ln; r = warp - BB * NN; }
    const float4* p = (const float4*)(src + (size_t)r * DD);
    float s = 0.f;
#pragma unroll
    for (int i = 0; i < 2; ++i) {
        float4 v = p[lane + 32 * i];
        s += v.x * v.x + v.y * v.y + v.z * v.z + v.w * v.w;
    }
#pragma unroll
    for (int o = 16; o; o >>= 1) s += __shfl_down_sync(0xffffffffu, s, o);
    if (lane == 0) dst[r] = s;
}

// ---------------- pwdist GEMM: pw = pn + ln - 2*P@L^T -----------------------
// 128x128 block tile, 8x8 per thread, K-chunks of 8, 256 threads.
__global__ __launch_bounds__(256) void pwdist_kernel(const float* __restrict__ P,
                                                     const float* __restrict__ L) {
    int b = blockIdx.z;
    int row0 = blockIdx.y * 128;
    int col0 = blockIdx.x * 128;
    const float* A  = P + (size_t)b * NN * DD;
    const float* Bm = L + (size_t)b * NN * DD;
    __shared__ float As[8][132];
    __shared__ float Bs[8][132];
    float acc[8][8];
#pragma unroll
    for (int i = 0; i < 8; ++i)
#pragma unroll
        for (int j = 0; j < 8; ++j) acc[i][j] = 0.f;

    int t = threadIdx.x;
    int lrow = t >> 1;           // 0..127
    int lk   = (t & 1) << 2;     // 0 or 4
    int tx = t & 15, ty = t >> 4;

    for (int k0 = 0; k0 < DD; k0 += 8) {
        float4 av = *(const float4*)(A  + (size_t)(row0 + lrow) * DD + k0 + lk);
        float4 bv = *(const float4*)(Bm + (size_t)(col0 + lrow) * DD + k0 + lk);
        __syncthreads();
        As[lk + 0][lrow] = av.x; As[lk + 1][lrow] = av.y;
        As[lk + 2][lrow] = av.z; As[lk + 3][lrow] = av.w;
        Bs[lk + 0][lrow] = bv.x; Bs[lk + 1][lrow] = bv.y;
        Bs[lk + 2][lrow] = bv.z; Bs[lk + 3][lrow] = bv.w;
        __syncthreads();
#pragma unroll
        for (int k = 0; k < 8; ++k) {
            float a[8], bb[8];
            *(float4*)(a)      = *(const float4*)&As[k][ty * 8];
            *(float4*)(a + 4)  = *(const float4*)&As[k][ty * 8 + 4];
            *(float4*)(bb)     = *(const float4*)&Bs[k][tx * 8];
            *(float4*)(bb + 4) = *(const float4*)&Bs[k][tx * 8 + 4];
#pragma unroll
            for (int i = 0; i < 8; ++i)
#pragma unroll
                for (int j = 0; j < 8; ++j) acc[i][j] += a[i] * bb[j];
        }
    }

    float pr[8], lc[8];
#pragma unroll
    for (int i = 0; i < 8; ++i) pr[i] = g_pn[b * NN + row0 + ty * 8 + i];
#pragma unroll
    for (int j = 0; j < 8; ++j) lc[j] = g_ln[b * NN + col0 + tx * 8 + j];
#pragma unroll
    for (int i = 0; i < 8; ++i) {
        float* dst = g_pw + ((size_t)b * NN + row0 + ty * 8 + i) * NN + col0 + tx * 8;
        float4 o0, o1;
        o0.x = pr[i] + lc[0] - 2.f * acc[i][0];
        o0.y = pr[i] + lc[1] - 2.f * acc[i][1];
        o0.z = pr[i] + lc[2] - 2.f * acc[i][2];
        o0.w = pr[i] + lc[3] - 2.f * acc[i][3];
        o1.x = pr[i] + lc[4] - 2.f * acc[i][4];
        o1.y = pr[i] + lc[5] - 2.f * acc[i][5];
        o1.z = pr[i] + lc[6] - 2.f * acc[i][6];
        o1.w = pr[i] + lc[7] - 2.f * acc[i][7];
        *(float4*)dst = o0;
        *(float4*)(dst + 4) = o1;
    }
}

// ---------------- P1: initial row sums S_r = sum_c exp(f*pw)*cost[c] -------
__global__ __launch_bounds__(256) void p1_kernel(float f, int par) {
    int b = blockIdx.y, r = blockIdx.x;
    int bN = b * NN;
    const float4* row4 = (const float4*)(g_pw + ((size_t)bN + r) * NN);
    const float4* co4  = (const float4*)(g_cost[par] + bN);
    int tid = threadIdx.x;
    float s = 0.f;
#pragma unroll
    for (int i = 0; i < 2; ++i) {
        int idx = tid + 256 * i;
        float4 v = row4[idx];
        float4 c = co4[idx];
        s += __expf(f * v.x) * c.x + __expf(f * v.y) * c.y +
             __expf(f * v.z) * c.z + __expf(f * v.w) * c.w;
    }
    s = block_reduce_sum(s);
    if (tid == 0) g_S[bN + r] = s;
}

// ---------------- P2: column sums T_c = sum_r b, W_c = sum_r b*pw ----------
// b = exp(f*pw)*cost[c] * curr[r]/(S_r+eps)
__global__ __launch_bounds__(256) void p2_kernel(float f, int par) {
    int b = blockIdx.z;
    int r0 = blockIdx.y * 512;
    int c = blockIdx.x * 256 + threadIdx.x;
    int bN = b * NN;
    __shared__ float s_inv[512];
    for (int j = threadIdx.x; j < 512; j += 256) {
        int r = r0 + j;
        s_inv[j] = g_curr[bN + r] / (g_S[bN + r] + EPSF);
    }
    __syncthreads();
    float costc = g_cost[par][bN + c];
    float t = 0.f, w = 0.f;
    const float* base = g_pw + ((size_t)bN + r0) * NN + c;
#pragma unroll 4
    for (int j = 0; j < 512; ++j) {
        float val = base[(size_t)j * NN];
        float bb = __expf(f * val) * costc * s_inv[j];
        t += bb;
        w += bb * val;
    }
    atomicAdd(&g_T[bN + c], t);
    atomicAdd(&g_W[bN + c], w);
}

// ---------------- P3: bid_wt, result accumulation, cost update, zero T/W ---
__global__ __launch_bounds__(256) void p3_kernel(int par, float* out) {
    int i = blockIdx.x * 256 + threadIdx.x;
    float T = g_T[i], W = g_W[i], cost = g_cost[par][i];
    float bw = fminf(cost / (T + EPSF), 1.f);
    g_bw[i] = bw;
    g_cost[par ^ 1][i] = fmaxf(cost - T * bw, 0.f);
    g_T[i] = 0.f;
    g_W[i] = 0.f;
    float contrib = W * bw;
    contrib = block_reduce_sum(contrib);
    if (threadIdx.x == 0) atomicAdd(out, contrib);
}

// ---------------- P4+P1 fused: currency update (iter i) + rowsum (iter i+1)
__global__ __launch_bounds__(256) void p4p1_kernel(float f, float fn, int par) {
    int b = blockIdx.y, r = blockIdx.x;
    int bN = b * NN;
    const float4* row4 = (const float4*)(g_pw + ((size_t)bN + r) * NN);
    const float4* co4  = (const float4*)(g_cost[par] + bN);
    const float4* cn4  = (const float4*)(g_cost[par ^ 1] + bN);
    const float4* bw4  = (const float4*)(g_bw + bN);
    int tid = threadIdx.x;
    float u = 0.f, s2 = 0.f;
#pragma unroll
    for (int i = 0; i < 2; ++i) {
        int idx = tid + 256 * i;
        float4 v  = row4[idx];
        float4 co = co4[idx];
        float4 bw = bw4[idx];
        float4 cn = cn4[idx];
        u  += __expf(f * v.x) * co.x * bw.x + __expf(f * v.y) * co.y * bw.y +
              __expf(f * v.z) * co.z * bw.z + __expf(f * v.w) * co.w * bw.w;
        s2 += __expf(fn * v.x) * cn.x + __expf(fn * v.y) * cn.y +
              __expf(fn * v.z) * cn.z + __expf(fn * v.w) * cn.w;
    }
    block_reduce_sum2(u, s2);
    if (tid == 0) {
        float curr = g_curr[bN + r];
        float inv = curr / (g_S[bN + r] + EPSF);
        g_curr[bN + r] = fmaxf(curr - u * inv, 0.f);
        g_S[bN + r] = s2;  // row sum for next iteration (uses new cost + new factor)
    }
}

// ---------------- launch ----------------------------------------------------
extern "C" void kernel_launch(void* const* d_in, const int* in_sizes, int n_in,
                              void* d_out, int out_size) {
    const float* preds  = (const float*)d_in[0];
    const float* labels = (const float*)d_in[1];
    float* out = (float*)d_out;

    init_kernel<<<(BB * NN + 255) / 256, 256>>>(out);
    norms_kernel<<<(2 * BB * NN) / 8, 256>>>(preds, labels);
    pwdist_kernel<<<dim3(NN / 128, NN / 128, BB), 256>>>(preds, labels);

    const float F[7] = {-256.f, -64.f, -16.f, -4.f, -1.f, -0.25f, 0.f};
    p1_kernel<<<dim3(NN, BB), 256>>>(F[0], 0);
    int par = 0;
    for (int i = 0; i < 7; ++i) {
        p2_kernel<<<dim3(NN / 256, 4, BB), 256>>>(F[i], par);
        p3_kernel<<<(BB * NN) / 256, 256>>>(par, out);
        if (i < 6) p4p1_kernel<<<dim3(NN, BB), 256>>>(F[i], F[i + 1], par);
        par ^= 1;
    }
}

// round 4
// speedup vs baseline: 3.2306x; 3.2306x over previous
#include <cuda_runtime.h>
#include <cuda_bf16.h>
#include <cstdint>

#define BB 16
#define NN 2048
#define DD 256
#define EPSF 1e-9f
#define SKIPT (-86.0f)

// ---------------- scratch (static __device__ globals; no allocation) --------
__device__ __align__(256) float g_pw[(size_t)BB * NN * NN];   // 268 MB
__device__ __align__(256) __nv_bfloat16 g_Phi[(size_t)BB * NN * DD];
__device__ __align__(256) __nv_bfloat16 g_Plo[(size_t)BB * NN * DD];
__device__ __align__(256) __nv_bfloat16 g_Lhi[(size_t)BB * NN * DD];
__device__ __align__(256) __nv_bfloat16 g_Llo[(size_t)BB * NN * DD];
__device__ __align__(16) float g_pn[BB * NN];
__device__ __align__(16) float g_ln[BB * NN];
__device__ __align__(16) float g_S[BB * NN];
__device__ __align__(16) float g_T[BB * NN];
__device__ __align__(16) float g_W[BB * NN];
__device__ __align__(16) float g_cost[2][BB * NN];
__device__ __align__(16) float g_curr[BB * NN];
__device__ __align__(16) float g_bw[BB * NN];
__device__ __align__(16) int   g_minpw[BB * NN];  // float bits, atomicMin (exact for floats of either sign here)
__device__ float g_costsum[BB];

// ---------------- PTX helpers (baseline sm_80-class only!) ------------------
__device__ __forceinline__ uint32_t smem_u32(const void* p) {
    uint32_t a;
    asm("{ .reg .u64 t; cvta.to.shared.u64 t, %1; cvt.u32.u64 %0, t; }" : "=r"(a) : "l"(p));
    return a;
}

__device__ __forceinline__ void cpa16(uint32_t dst, const void* src) {
    asm volatile("cp.async.cg.shared.global [%0], [%1], 16;" :: "r"(dst), "l"(src));
}
__device__ __forceinline__ void cpa_commit() {
    asm volatile("cp.async.commit_group;" ::: "memory");
}
template <int N>
__device__ __forceinline__ void cpa_wait() {
    asm volatile("cp.async.wait_group %0;" :: "n"(N) : "memory");
}

#define LDSM4(r, addr) \
    asm volatile("ldmatrix.sync.aligned.m8n8.x4.shared.b16 {%0,%1,%2,%3}, [%4];" \
                 : "=r"((r)[0]), "=r"((r)[1]), "=r"((r)[2]), "=r"((r)[3]) : "r"(addr))

#define MMA_BF16(d, a, b) \
    asm volatile("mma.sync.aligned.m16n8k16.row.col.f32.bf16.bf16.f32 " \
                 "{%0,%1,%2,%3}, {%4,%5,%6,%7}, {%8,%9}, {%0,%1,%2,%3};" \
                 : "+f"((d)[0]), "+f"((d)[1]), "+f"((d)[2]), "+f"((d)[3]) \
                 : "r"((a)[0]), "r"((a)[1]), "r"((a)[2]), "r"((a)[3]), \
                   "r"((b)[0]), "r"((b)[1]))

// ---------------- reductions ------------------------------------------------
__device__ __forceinline__ float block_reduce_sum(float v) {
    __shared__ float red[8];
    int lane = threadIdx.x & 31, warp = threadIdx.x >> 5;
#pragma unroll
    for (int o = 16; o; o >>= 1) v += __shfl_down_sync(0xffffffffu, v, o);
    if (lane == 0) red[warp] = v;
    __syncthreads();
    if (warp == 0) {
        v = (lane < 8) ? red[lane] : 0.f;
#pragma unroll
        for (int o = 4; o; o >>= 1) v += __shfl_down_sync(0xffffffffu, v, o);
    }
    return v;  // thread 0
}

// ---------------- init ------------------------------------------------------
__global__ void init_kernel(float* out) {
    int i = blockIdx.x * blockDim.x + threadIdx.x;
    if (i < BB * NN) {
        g_cost[0][i] = 1.f;
        g_curr[i] = 1.f;
        g_T[i] = 0.f;
        g_W[i] = 0.f;
        g_minpw[i] = 0x7f800000;  // +inf
    }
    if (i == 0) out[0] = 0.f;
}

// ---------------- split to bf16 hi/lo + row norms (warp per row) ------------
__global__ __launch_bounds__(256) void split_norms_kernel(const float* __restrict__ P,
                                                          const float* __restrict__ L) {
    int warp = (blockIdx.x * blockDim.x + threadIdx.x) >> 5;
    int lane = threadIdx.x & 31;
    const float* src;
    __nv_bfloat16 *dhi, *dlo;
    float* dn;
    int r;
    if (warp < BB * NN) { src = P; dhi = g_Phi; dlo = g_Plo; dn = g_pn; r = warp; }
    else { src = L; dhi = g_Lhi; dlo = g_Llo; dn = g_ln; r = warp - BB * NN; }
    const float4* p = (const float4*)(src + (size_t)r * DD);
    float s = 0.f;
#pragma unroll
    for (int i = 0; i < 2; ++i) {
        int idx = lane + 32 * i;
        float4 v = p[idx];
        s += v.x * v.x + v.y * v.y + v.z * v.z + v.w * v.w;
        __nv_bfloat16 h0 = __float2bfloat16(v.x), h1 = __float2bfloat16(v.y);
        __nv_bfloat16 h2 = __float2bfloat16(v.z), h3 = __float2bfloat16(v.w);
        __nv_bfloat16 l0 = __float2bfloat16(v.x - __bfloat162float(h0));
        __nv_bfloat16 l1 = __float2bfloat16(v.y - __bfloat162float(h1));
        __nv_bfloat16 l2 = __float2bfloat16(v.z - __bfloat162float(h2));
        __nv_bfloat16 l3 = __float2bfloat16(v.w - __bfloat162float(h3));
        uint2 ph, pl;
        ph.x = ((uint32_t)__bfloat16_as_ushort(h1) << 16) | __bfloat16_as_ushort(h0);
        ph.y = ((uint32_t)__bfloat16_as_ushort(h3) << 16) | __bfloat16_as_ushort(h2);
        pl.x = ((uint32_t)__bfloat16_as_ushort(l1) << 16) | __bfloat16_as_ushort(l0);
        pl.y = ((uint32_t)__bfloat16_as_ushort(l3) << 16) | __bfloat16_as_ushort(l2);
        *(uint2*)(dhi + (size_t)r * DD + idx * 4) = ph;
        *(uint2*)(dlo + (size_t)r * DD + idx * 4) = pl;
    }
#pragma unroll
    for (int o = 16; o; o >>= 1) s += __shfl_down_sync(0xffffffffu, s, o);
    if (lane == 0) dn[r] = s;
}

// ---------------- mma.sync GEMM: pw = pn + ln - 2*(P@L^T) -------------------
// CTA tile 128x128, K chunks of 64, 2-stage cp.async pipeline.
// bf16 2-term split: hi*hi + hi*lo + lo*hi.
// smem per stage: Ahi,Alo,Bhi,Blo each 128 rows x 64 bf16 (128B rows),
// 16B-unit XOR swizzle: unit stored at (u ^ (r&7)).
#define STAGE_BYTES 65536
#define ARR_BYTES 16384
#define SMEM_MM (2 * STAGE_BYTES)

__global__ __launch_bounds__(256) void mm_kernel() {
    extern __shared__ char smem[];
    uint32_t sb = smem_u32(smem);
    int tid = threadIdx.x, lane = tid & 31, wid = tid >> 5;
    int wm = wid & 1, wn = wid >> 1;   // warp tile: rows wm*64(+64), cols wn*32(+32)
    int b = blockIdx.z;
    int row0 = blockIdx.y * 128;
    int col0 = blockIdx.x * 128;
    int bN = b * NN;

    const char* gA_hi = (const char*)(g_Phi + ((size_t)bN + row0) * DD);
    const char* gA_lo = (const char*)(g_Plo + ((size_t)bN + row0) * DD);
    const char* gB_hi = (const char*)(g_Lhi + ((size_t)bN + col0) * DD);
    const char* gB_lo = (const char*)(g_Llo + ((size_t)bN + col0) * DD);

    // per-thread load slots: 16 x 16B over (arr, row, unit)
    // v = tid + 256*it ; u = v&7, r = (v>>3)&127, arr = v>>10
    auto issue_loads = [&](int kc, int stage) {
        const char* srcs[4] = { gA_hi, gA_lo, gB_hi, gB_lo };
        uint32_t base = sb + stage * STAGE_BYTES;
#pragma unroll
        for (int it = 0; it < 16; ++it) {
            int v = tid + 256 * it;
            int u = v & 7, r = (v >> 3) & 127, arr = v >> 10;
            uint32_t dst = base + arr * ARR_BYTES + r * 128 + ((u ^ (r & 7)) << 4);
            const char* src = srcs[arr] + (size_t)r * (DD * 2) + kc * 128 + u * 16;
            cpa16(dst, src);
        }
        cpa_commit();
    };

    float acc[4][4][4];
#pragma unroll
    for (int mi = 0; mi < 4; ++mi)
#pragma unroll
        for (int ni = 0; ni < 4; ++ni)
#pragma unroll
            for (int q = 0; q < 4; ++q) acc[mi][ni][q] = 0.f;

    // ldmatrix per-thread address pieces
    int rA = lane & 15, uA = lane >> 4;                     // A: rows m, k-unit half
    int rB = (lane & 7) | ((lane >> 4) << 3), uB = (lane >> 3) & 1;
    uint32_t aRowOff = (uint32_t)(wm * 64 + rA) * 128;
    uint32_t bRowOff = (uint32_t)(wn * 32 + rB) * 128;
    int aMask = rA & 7, bMask = rB & 7;

    issue_loads(0, 0);

#pragma unroll 1
    for (int kc = 0; kc < 4; ++kc) {
        int stage = kc & 1;
        if (kc < 3) issue_loads(kc + 1, stage ^ 1);
        if (kc < 3) cpa_wait<1>(); else cpa_wait<0>();
        __syncthreads();

        uint32_t sbase = sb + stage * STAGE_BYTES;
        uint32_t aHiB = sbase + aRowOff;
        uint32_t aLoB = sbase + ARR_BYTES + aRowOff;
        uint32_t bHiB = sbase + 2 * ARR_BYTES + bRowOff;
        uint32_t bLoB = sbase + 3 * ARR_BYTES + bRowOff;

#pragma unroll
        for (int ks = 0; ks < 4; ++ks) {
            uint32_t suA = (uint32_t)(((ks * 2 + uA) ^ aMask) << 4);
            uint32_t suB = (uint32_t)(((ks * 2 + uB) ^ bMask) << 4);
            uint32_t ahi[4][4], alo[4][4], bhi[2][4], blo[2][4];
#pragma unroll
            for (int mi = 0; mi < 4; ++mi) {
                LDSM4(ahi[mi], aHiB + mi * (16 * 128) + suA);
                LDSM4(alo[mi], aLoB + mi * (16 * 128) + suA);
            }
#pragma unroll
            for (int bi = 0; bi < 2; ++bi) {
                LDSM4(bhi[bi], bHiB + bi * (16 * 128) + suB);
                LDSM4(blo[bi], bLoB + bi * (16 * 128) + suB);
            }
#pragma unroll
            for (int mi = 0; mi < 4; ++mi)
#pragma unroll
                for (int ni = 0; ni < 4; ++ni) {
                    uint32_t* bh = &bhi[ni >> 1][(ni & 1) * 2];
                    uint32_t* bl = &blo[ni >> 1][(ni & 1) * 2];
                    MMA_BF16(acc[mi][ni], ahi[mi], bh);
                    MMA_BF16(acc[mi][ni], ahi[mi], bl);
                    MMA_BF16(acc[mi][ni], alo[mi], bh);
                }
        }
        __syncthreads();
    }

    // epilogue: pw = pn + ln - 2*acc ; track per-row min
    int q = lane >> 2, cq = (lane & 3) * 2;
#pragma unroll
    for (int mi = 0; mi < 4; ++mi) {
        int grow0 = row0 + wm * 64 + mi * 16 + q;
        float pn0 = g_pn[bN + grow0];
        float pn1 = g_pn[bN + grow0 + 8];
        float mn0 = 3.0e38f, mn1 = 3.0e38f;
        float* orow0 = g_pw + ((size_t)(bN + grow0)) * NN + col0 + wn * 32;
        float* orow1 = orow0 + (size_t)8 * NN;
#pragma unroll
        for (int ni = 0; ni < 4; ++ni) {
            int gc = col0 + wn * 32 + ni * 8 + cq;
            float2 lnv = *(const float2*)(g_ln + bN + gc);
            float2 o0, o1;
            o0.x = pn0 + lnv.x - 2.f * acc[mi][ni][0];
            o0.y = pn0 + lnv.y - 2.f * acc[mi][ni][1];
            o1.x = pn1 + lnv.x - 2.f * acc[mi][ni][2];
            o1.y = pn1 + lnv.y - 2.f * acc[mi][ni][3];
            mn0 = fminf(mn0, fminf(o0.x, o0.y));
            mn1 = fminf(mn1, fminf(o1.x, o1.y));
            *(float2*)(orow0 + ni * 8 + cq) = o0;
            *(float2*)(orow1 + ni * 8 + cq) = o1;
        }
        // reduce min over the 4 lanes sharing each row (lane bits 0-1)
#pragma unroll
        for (int o = 1; o <= 2; o <<= 1) {
            mn0 = fminf(mn0, __shfl_xor_sync(0xffffffffu, mn0, o));
            mn1 = fminf(mn1, __shfl_xor_sync(0xffffffffu, mn1, o));
        }
        if ((lane & 3) == 0) {
            atomicMin(&g_minpw[bN + grow0], __float_as_int(mn0));
            atomicMin(&g_minpw[bN + grow0 + 8], __float_as_int(mn1));
        }
    }
}

// ---------------- P1: initial row sums (4 rows/block, 64 threads/row) -------
__global__ __launch_bounds__(256) void p1_kernel(float f, int par) {
    int b = blockIdx.y, bN = b * NN;
    int tid = threadIdx.x, gid = tid >> 6, gtid = tid & 63;
    int r = blockIdx.x * 4 + gid;
    float minv = __int_as_float(g_minpw[bN + r]);
    bool need = !(f * minv < SKIPT);
    float s = 0.f;
    if (need) {
        const float4* row4 = (const float4*)(g_pw + ((size_t)bN + r) * NN);
        const float4* co4 = (const float4*)(g_cost[par] + bN);
#pragma unroll
        for (int i = 0; i < 8; ++i) {
            int idx = gtid + 64 * i;
            float4 v = row4[idx];
            float4 c = co4[idx];
            s += __expf(f * v.x) * c.x + __expf(f * v.y) * c.y +
                 __expf(f * v.z) * c.z + __expf(f * v.w) * c.w;
        }
    }
    __shared__ float smA[8];
#pragma unroll
    for (int o = 16; o; o >>= 1) s += __shfl_down_sync(0xffffffffu, s, o);
    if ((tid & 31) == 0) smA[tid >> 5] = s;
    __syncthreads();
    if (gtid == 0) g_S[bN + r] = need ? (smA[2 * gid] + smA[2 * gid + 1]) : 0.f;
}

// ---------------- P2: column sums T, W with per-row underflow skip ---------
__global__ __launch_bounds__(256) void p2_kernel(float f, int par) {
    int b = blockIdx.z;
    int r0 = blockIdx.y * 512;
    int c = blockIdx.x * 256 + threadIdx.x;
    int bN = b * NN;
    __shared__ float s_inv[512];
    __shared__ unsigned char s_flag[512];
    __shared__ int s_cnt;
    if (threadIdx.x == 0) s_cnt = 0;
    __syncthreads();
    int loc = 0;
    for (int j = threadIdx.x; j < 512; j += 256) {
        int r = r0 + j;
        float minv = __int_as_float(g_minpw[bN + r]);
        bool fl = (f * minv < SKIPT);
        s_flag[j] = fl;
        loc += fl;
        s_inv[j] = g_curr[bN + r] / (g_S[bN + r] + EPSF);
    }
    atomicAdd(&s_cnt, loc);
    __syncthreads();
    if (s_cnt == 512) return;
    float costc = g_cost[par][bN + c];
    float t = 0.f, w = 0.f;
    const float* base = g_pw + ((size_t)bN + r0) * NN + c;
    for (int j = 0; j < 512; ++j) {
        if (s_flag[j]) continue;
        float val = base[(size_t)j * NN];
        float bb = __expf(f * val) * costc * s_inv[j];
        t += bb;
        w += bb * val;
    }
    atomicAdd(&g_T[bN + c], t);
    atomicAdd(&g_W[bN + c], w);
}

// ---------------- P3: bid_wt, result accumulation, cost update --------------
__global__ __launch_bounds__(256) void p3_kernel(int par, float* out) {
    int i = blockIdx.x * 256 + threadIdx.x;
    float T = g_T[i], W = g_W[i], cost = g_cost[par][i];
    float bw = fminf(cost / (T + EPSF), 1.f);
    g_bw[i] = bw;
    g_cost[par ^ 1][i] = fmaxf(cost - T * bw, 0.f);
    g_T[i] = 0.f;
    g_W[i] = 0.f;
    float contrib = block_reduce_sum(W * bw);
    if (threadIdx.x == 0) atomicAdd(out, contrib);
}

// ---------------- sum of new cost per batch (for f_next == 0 shortcut) ------
__global__ __launch_bounds__(256) void sumcost_kernel(int parNew) {
    int b = blockIdx.x;
    float s = 0.f;
    const float4* c4 = (const float4*)(g_cost[parNew] + b * NN);
    for (int i = threadIdx.x; i < 512; i += 256) {
        float4 v = c4[i];
        s += v.x + v.y + v.z + v.w;
    }
    s = block_reduce_sum(s);
    if (threadIdx.x == 0) g_costsum[b] = s;
}

// ---------------- P4+P1 fused: currency update + next row sums --------------
__global__ __launch_bounds__(256) void p4p1_kernel(float f, float fn, int par) {
    int b = blockIdx.y, bN = b * NN;
    int tid = threadIdx.x, gid = tid >> 6, gtid = tid & 63;
    int r = blockIdx.x * 4 + gid;
    float minv = __int_as_float(g_minpw[bN + r]);
    bool needU = !(f * minv < SKIPT);
    bool fnz = (fn == 0.0f);
    bool needS = (!fnz) && !(fn * minv < SKIPT);
    float u = 0.f, s2 = 0.f;
    if (needU || needS) {
        const float4* row4 = (const float4*)(g_pw + ((size_t)bN + r) * NN);
        const float4* co4 = (const float4*)(g_cost[par] + bN);
        const float4* cn4 = (const float4*)(g_cost[par ^ 1] + bN);
        const float4* bw4 = (const float4*)(g_bw + bN);
#pragma unroll
        for (int i = 0; i < 8; ++i) {
            int idx = gtid + 64 * i;
            float4 v = row4[idx];
            if (needU) {
                float4 co = co4[idx];
                float4 bw = bw4[idx];
                u += __expf(f * v.x) * co.x * bw.x + __expf(f * v.y) * co.y * bw.y +
                     __expf(f * v.z) * co.z * bw.z + __expf(f * v.w) * co.w * bw.w;
            }
            if (needS) {
                float4 cn = cn4[idx];
                s2 += __expf(fn * v.x) * cn.x + __expf(fn * v.y) * cn.y +
                      __expf(fn * v.z) * cn.z + __expf(fn * v.w) * cn.w;
            }
        }
    }
    __shared__ float smA[8], smB[8];
#pragma unroll
    for (int o = 16; o; o >>= 1) {
        u += __shfl_down_sync(0xffffffffu, u, o);
        s2 += __shfl_down_sync(0xffffffffu, s2, o);
    }
    if ((tid & 31) == 0) { smA[tid >> 5] = u; smB[tid >> 5] = s2; }
    __syncthreads();
    if (gtid == 0) {
        float uu = smA[2 * gid] + smA[2 * gid + 1];
        float ss = smB[2 * gid] + smB[2 * gid + 1];
        if (needU) {
            float curr = g_curr[bN + r];
            float inv = curr / (g_S[bN + r] + EPSF);
            g_curr[bN + r] = fmaxf(curr - uu * inv, 0.f);
        }
        g_S[bN + r] = fnz ? g_costsum[b] : (needS ? ss : 0.f);
    }
}

// ---------------- launch ----------------------------------------------------
extern "C" void kernel_launch(void* const* d_in, const int* in_sizes, int n_in,
                              void* d_out, int out_size) {
    const float* preds = (const float*)d_in[0];
    const float* labels = (const float*)d_in[1];
    float* out = (float*)d_out;

    cudaFuncSetAttribute(mm_kernel, cudaFuncAttributeMaxDynamicSharedMemorySize, SMEM_MM);

    init_kernel<<<(BB * NN + 255) / 256, 256>>>(out);
    split_norms_kernel<<<(2 * BB * NN) / 8, 256>>>(preds, labels);
    mm_kernel<<<dim3(NN / 128, NN / 128, BB), 256, SMEM_MM>>>();

    const float F[7] = {-256.f, -64.f, -16.f, -4.f, -1.f, -0.25f, 0.f};
    p1_kernel<<<dim3(NN / 4, BB), 256>>>(F[0], 0);
    int par = 0;
    for (int i = 0; i < 7; ++i) {
        p2_kernel<<<dim3(NN / 256, 4, BB), 256>>>(F[i], par);
        p3_kernel<<<(BB * NN) / 256, 256>>>(par, out);
        if (i < 6) {
            if (F[i + 1] == 0.f) sumcost_kernel<<<BB, 256>>>(par ^ 1);
            p4p1_kernel<<<dim3(NN / 4, BB), 256>>>(F[i], F[i + 1], par);
        }
        par ^= 1;
    }
}

// round 5
// speedup vs baseline: 12.6579x; 3.9181x over previous
#include <cuda_runtime.h>
#include <cuda_bf16.h>
#include <cstdint>

#define BB 16
#define NN 2048
#define DD 256
#define EPSF 1e-9f
#define SKIPT (-46.0f)
#define NF 6

// ---------------- scratch (static __device__ globals; no allocation) --------
__device__ __align__(256) __nv_bfloat16 g_Phi[(size_t)BB * NN * DD];
__device__ __align__(256) __nv_bfloat16 g_Lhi[(size_t)BB * NN * DD];
__device__ __align__(16) float g_pn[BB * NN];
__device__ __align__(16) float g_ln[BB * NN];
__device__ __align__(16) float g_T[BB * NN];
__device__ __align__(16) float g_W[BB * NN];
__device__ __align__(16) float g_cost[BB * NN];
__device__ __align__(16) float g_curr[BB * NN];
__device__ __align__(16) float g_bw[BB * NN];
__device__ __align__(16) float g_wrow[BB * NN];
__device__ __align__(16) int   g_minpw[BB * NN];   // float bits for atomicMin
__device__ int   g_act[NF][BB * NN];
__device__ int   g_nact[NF];
__device__ float g_costsum[BB];
__device__ float g_u[BB * DD];
__device__ float g_SW[BB];
__device__ float g_SWPN[BB];

__constant__ float c_F[NF] = {-256.f, -64.f, -16.f, -4.f, -1.f, -0.25f};

// ---------------- PTX helpers (baseline sm_80-class only) -------------------
__device__ __forceinline__ uint32_t smem_u32(const void* p) {
    uint32_t a;
    asm("{ .reg .u64 t; cvta.to.shared.u64 t, %1; cvt.u32.u64 %0, t; }" : "=r"(a) : "l"(p));
    return a;
}
__device__ __forceinline__ void cpa16(uint32_t dst, const void* src) {
    asm volatile("cp.async.cg.shared.global [%0], [%1], 16;" :: "r"(dst), "l"(src));
}
__device__ __forceinline__ void cpa_commit() {
    asm volatile("cp.async.commit_group;" ::: "memory");
}
template <int N>
__device__ __forceinline__ void cpa_wait() {
    asm volatile("cp.async.wait_group %0;" :: "n"(N) : "memory");
}

#define LDSM4(r, addr) \
    asm volatile("ldmatrix.sync.aligned.m8n8.x4.shared.b16 {%0,%1,%2,%3}, [%4];" \
                 : "=r"((r)[0]), "=r"((r)[1]), "=r"((r)[2]), "=r"((r)[3]) : "r"(addr))

#define MMA_BF16(d, a, b) \
    asm volatile("mma.sync.aligned.m16n8k16.row.col.f32.bf16.bf16.f32 " \
                 "{%0,%1,%2,%3}, {%4,%5,%6,%7}, {%8,%9}, {%0,%1,%2,%3};" \
                 : "+f"((d)[0]), "+f"((d)[1]), "+f"((d)[2]), "+f"((d)[3]) \
                 : "r"((a)[0]), "r"((a)[1]), "r"((a)[2]), "r"((a)[3]), \
                   "r"((b)[0]), "r"((b)[1]))

// ---------------- reductions ------------------------------------------------
__device__ __forceinline__ float block_reduce_256(float v) {
    __shared__ float red[8];
    int lane = threadIdx.x & 31, warp = threadIdx.x >> 5;
#pragma unroll
    for (int o = 16; o; o >>= 1) v += __shfl_down_sync(0xffffffffu, v, o);
    if (lane == 0) red[warp] = v;
    __syncthreads();
    if (warp == 0) {
        v = (lane < 8) ? red[lane] : 0.f;
#pragma unroll
        for (int o = 4; o; o >>= 1) v += __shfl_down_sync(0xffffffffu, v, o);
    }
    return v;  // thread 0
}

__device__ float block_reduce_1024_bcast(float v) {
    __shared__ float red[32];
    int lane = threadIdx.x & 31, warp = threadIdx.x >> 5;
#pragma unroll
    for (int o = 16; o; o >>= 1) v += __shfl_down_sync(0xffffffffu, v, o);
    if (lane == 0) red[warp] = v;
    __syncthreads();
    if (warp == 0) {
        v = red[lane];
#pragma unroll
        for (int o = 16; o; o >>= 1) v += __shfl_down_sync(0xffffffffu, v, o);
        if (lane == 0) red[0] = v;
    }
    __syncthreads();
    float r = red[0];
    __syncthreads();
    return r;
}

// ---------------- init ------------------------------------------------------
__global__ void init_kernel(float* out) {
    int i = blockIdx.x * blockDim.x + threadIdx.x;
    if (i < BB * NN) {
        g_cost[i] = 1.f;
        g_curr[i] = 1.f;
        g_T[i] = 0.f;
        g_W[i] = 0.f;
        g_minpw[i] = 0x7f800000;  // +inf
    }
    if (i < BB * DD) g_u[i] = 0.f;
    if (i < NF) g_nact[i] = 0;
    if (i < BB) { g_SW[i] = 0.f; g_SWPN[i] = 0.f; }
    if (i == 0) out[0] = 0.f;
}

// ---------------- split to bf16 hi + row norms (warp per row) ---------------
__global__ __launch_bounds__(256) void split_norms_kernel(const float* __restrict__ P,
                                                          const float* __restrict__ L) {
    int warp = (blockIdx.x * blockDim.x + threadIdx.x) >> 5;
    int lane = threadIdx.x & 31;
    const float* src;
    __nv_bfloat16* dhi;
    float* dn;
    int r;
    if (warp < BB * NN) { src = P; dhi = g_Phi; dn = g_pn; r = warp; }
    else { src = L; dhi = g_Lhi; dn = g_ln; r = warp - BB * NN; }
    const float4* p = (const float4*)(src + (size_t)r * DD);
    float s = 0.f;
#pragma unroll
    for (int i = 0; i < 2; ++i) {
        int idx = lane + 32 * i;
        float4 v = p[idx];
        s += v.x * v.x + v.y * v.y + v.z * v.z + v.w * v.w;
        __nv_bfloat16 h0 = __float2bfloat16(v.x), h1 = __float2bfloat16(v.y);
        __nv_bfloat16 h2 = __float2bfloat16(v.z), h3 = __float2bfloat16(v.w);
        uint2 ph;
        ph.x = ((uint32_t)__bfloat16_as_ushort(h1) << 16) | __bfloat16_as_ushort(h0);
        ph.y = ((uint32_t)__bfloat16_as_ushort(h3) << 16) | __bfloat16_as_ushort(h2);
        *(uint2*)(dhi + (size_t)r * DD + idx * 4) = ph;
    }
#pragma unroll
    for (int o = 16; o; o >>= 1) s += __shfl_down_sync(0xffffffffu, s, o);
    if (lane == 0) dn[r] = s;
}

// ---------------- min-GEMM: rowmin of pw = pn + ln - 2*(P@L^T), no stores ---
#define STAGE_BYTES 32768
#define ARR_BYTES 16384
#define SMEM_MM (2 * STAGE_BYTES)

__global__ __launch_bounds__(256) void minpw_kernel() {
    extern __shared__ char smem[];
    uint32_t sb = smem_u32(smem);
    int tid = threadIdx.x, lane = tid & 31, wid = tid >> 5;
    int wm = wid & 1, wn = wid >> 1;
    int b = blockIdx.z;
    int row0 = blockIdx.y * 128;
    int col0 = blockIdx.x * 128;
    int bN = b * NN;

    const char* gA = (const char*)(g_Phi + ((size_t)bN + row0) * DD);
    const char* gB = (const char*)(g_Lhi + ((size_t)bN + col0) * DD);

    auto issue_loads = [&](int kc, int stage) {
        const char* srcs[2] = { gA, gB };
        uint32_t base = sb + stage * STAGE_BYTES;
#pragma unroll
        for (int it = 0; it < 8; ++it) {
            int v = tid + 256 * it;
            int u = v & 7, r = (v >> 3) & 127, arr = v >> 10;
            uint32_t dst = base + arr * ARR_BYTES + r * 128 + ((u ^ (r & 7)) << 4);
            const char* src = srcs[arr] + (size_t)r * (DD * 2) + kc * 128 + u * 16;
            cpa16(dst, src);
        }
        cpa_commit();
    };

    float acc[4][4][4];
#pragma unroll
    for (int mi = 0; mi < 4; ++mi)
#pragma unroll
        for (int ni = 0; ni < 4; ++ni)
#pragma unroll
            for (int q = 0; q < 4; ++q) acc[mi][ni][q] = 0.f;

    int rA = lane & 15, uA = lane >> 4;
    int rB = (lane & 7) | ((lane >> 4) << 3), uB = (lane >> 3) & 1;
    uint32_t aRowOff = (uint32_t)(wm * 64 + rA) * 128;
    uint32_t bRowOff = (uint32_t)(wn * 32 + rB) * 128;
    int aMask = rA & 7, bMask = rB & 7;

    issue_loads(0, 0);

#pragma unroll 1
    for (int kc = 0; kc < 4; ++kc) {
        int stage = kc & 1;
        if (kc < 3) issue_loads(kc + 1, stage ^ 1);
        if (kc < 3) cpa_wait<1>(); else cpa_wait<0>();
        __syncthreads();

        uint32_t sbase = sb + stage * STAGE_BYTES;
        uint32_t aB = sbase + aRowOff;
        uint32_t bB = sbase + ARR_BYTES + bRowOff;

#pragma unroll
        for (int ks = 0; ks < 4; ++ks) {
            uint32_t suA = (uint32_t)(((ks * 2 + uA) ^ aMask) << 4);
            uint32_t suB = (uint32_t)(((ks * 2 + uB) ^ bMask) << 4);
            uint32_t ahi[4][4], bhi[2][4];
#pragma unroll
            for (int mi = 0; mi < 4; ++mi) LDSM4(ahi[mi], aB + mi * (16 * 128) + suA);
#pragma unroll
            for (int bi = 0; bi < 2; ++bi) LDSM4(bhi[bi], bB + bi * (16 * 128) + suB);
#pragma unroll
            for (int mi = 0; mi < 4; ++mi)
#pragma unroll
                for (int ni = 0; ni < 4; ++ni)
                    MMA_BF16(acc[mi][ni], ahi[mi], &bhi[ni >> 1][(ni & 1) * 2]);
        }
        __syncthreads();
    }

    // epilogue: min over row of pn + ln - 2*acc (no pw store)
    int q = lane >> 2, cq = (lane & 3) * 2;
#pragma unroll
    for (int mi = 0; mi < 4; ++mi) {
        int grow0 = row0 + wm * 64 + mi * 16 + q;
        float pn0 = g_pn[bN + grow0];
        float pn1 = g_pn[bN + grow0 + 8];
        float mn0 = 3.0e38f, mn1 = 3.0e38f;
#pragma unroll
        for (int ni = 0; ni < 4; ++ni) {
            int gc = col0 + wn * 32 + ni * 8 + cq;
            float2 lnv = *(const float2*)(g_ln + bN + gc);
            mn0 = fminf(mn0, fminf(pn0 + lnv.x - 2.f * acc[mi][ni][0],
                                   pn0 + lnv.y - 2.f * acc[mi][ni][1]));
            mn1 = fminf(mn1, fminf(pn1 + lnv.x - 2.f * acc[mi][ni][2],
                                   pn1 + lnv.y - 2.f * acc[mi][ni][3]));
        }
#pragma unroll
        for (int o = 1; o <= 2; o <<= 1) {
            mn0 = fminf(mn0, __shfl_xor_sync(0xffffffffu, mn0, o));
            mn1 = fminf(mn1, __shfl_xor_sync(0xffffffffu, mn1, o));
        }
        if ((lane & 3) == 0) {
            atomicMin(&g_minpw[bN + grow0], __float_as_int(mn0));
            atomicMin(&g_minpw[bN + grow0 + 8], __float_as_int(mn1));
        }
    }
}

// ---------------- compact: active-row lists per negative-f iteration --------
__global__ __launch_bounds__(256) void compact_kernel() {
    int i = blockIdx.x * 256 + threadIdx.x;
    float minv = __int_as_float(g_minpw[i]);
#pragma unroll
    for (int j = 0; j < NF; ++j) {
        if (c_F[j] * minv >= SKIPT) {
            int p = atomicAdd(&g_nact[j], 1);
            g_act[j][p] = i;
        }
    }
}

// ---------------- rare path: exact auction for active rows (expected none) --
__device__ void compute_pwrow(const float* __restrict__ P, const float* __restrict__ L,
                              int r, int bN, float* pwrow) {
    int lane = threadIdx.x & 31, wid = threadIdx.x >> 5;
    const float4* prow4 = (const float4*)(P + (size_t)r * DD);
    float4 pv0 = prow4[lane * 2], pv1 = prow4[lane * 2 + 1];
    float pnv = g_pn[r];
    for (int c = wid; c < NN; c += 32) {
        const float4* lrow = (const float4*)(L + ((size_t)bN + c) * DD);
        float4 l0 = lrow[lane * 2], l1 = lrow[lane * 2 + 1];
        float d = pv0.x * l0.x + pv0.y * l0.y + pv0.z * l0.z + pv0.w * l0.w +
                  pv1.x * l1.x + pv1.y * l1.y + pv1.z * l1.z + pv1.w * l1.w;
#pragma unroll
        for (int o = 16; o; o >>= 1) d += __shfl_down_sync(0xffffffffu, d, o);
        if (lane == 0) pwrow[c] = pnv + g_ln[bN + c] - 2.f * d;
    }
}

__global__ __launch_bounds__(1024) void rare_kernel(const float* __restrict__ P,
                                                    const float* __restrict__ L,
                                                    float* out) {
    __shared__ float pwrow[NN];
    __shared__ int aff[BB];
    int tid = threadIdx.x;
    for (int j = 0; j < NF; ++j) {
        int n = g_nact[j];
        if (n == 0) continue;
        float f = c_F[j];
        if (tid < BB) aff[tid] = 0;
        __syncthreads();
        // Phase A: per active row -> S, w, accumulate T/W (cost is OLD cost)
        for (int idx = 0; idx < n; ++idx) {
            int r = g_act[j][idx];
            int b = r >> 11, bN = b * NN;
            compute_pwrow(P, L, r, bN, pwrow);
            __syncthreads();
            float s = 0.f;
            for (int c = tid; c < NN; c += 1024) s += __expf(f * pwrow[c]) * g_cost[bN + c];
            s = block_reduce_1024_bcast(s);
            float w = g_curr[r] / (s + EPSF);
            if (tid == 0) { g_wrow[r] = w; aff[b] = 1; }
            for (int c = tid; c < NN; c += 1024) {
                float bb = __expf(f * pwrow[c]) * g_cost[bN + c] * w;
                g_T[bN + c] += bb;
                g_W[bN + c] += bb * pwrow[c];
            }
            __syncthreads();
        }
        // Phase B: bw + result contribution over affected batches
        float contrib = 0.f;
        for (int b = 0; b < BB; ++b) {
            if (!aff[b]) continue;
            int bN = b * NN;
            for (int c = tid; c < NN; c += 1024) {
                float T = g_T[bN + c], W = g_W[bN + c], co = g_cost[bN + c];
                float bw = fminf(co / (T + EPSF), 1.f);
                g_bw[bN + c] = bw;
                contrib += W * bw;
            }
        }
        contrib = block_reduce_1024_bcast(contrib);
        if (tid == 0) atomicAdd(out, contrib);
        // Phase C: currency update per active row (uses OLD cost + bw)
        for (int idx = 0; idx < n; ++idx) {
            int r = g_act[j][idx];
            int b = r >> 11, bN = b * NN;
            compute_pwrow(P, L, r, bN, pwrow);
            __syncthreads();
            float u = 0.f;
            for (int c = tid; c < NN; c += 1024)
                u += __expf(f * pwrow[c]) * g_cost[bN + c] * g_bw[bN + c];
            u = block_reduce_1024_bcast(u);
            if (tid == 0) g_curr[r] = fmaxf(g_curr[r] - u * g_wrow[r], 0.f);
            __syncthreads();
        }
        // Phase D: cost update (in place, last) + zero T/W
        for (int b = 0; b < BB; ++b) {
            if (!aff[b]) continue;
            int bN = b * NN;
            for (int c = tid; c < NN; c += 1024) {
                float T = g_T[bN + c];
                g_cost[bN + c] = fmaxf(g_cost[bN + c] - T * g_bw[bN + c], 0.f);
                g_T[bN + c] = 0.f;
                g_W[bN + c] = 0.f;
            }
        }
        __syncthreads();
    }
}

// ---------------- f==0 closed form ------------------------------------------
__global__ __launch_bounds__(256) void costsum_kernel() {
    int b = blockIdx.x;
    float s = 0.f;
    const float4* c4 = (const float4*)(g_cost + b * NN);
    for (int i = threadIdx.x; i < NN / 4; i += 256) {
        float4 v = c4[i];
        s += v.x + v.y + v.z + v.w;
    }
    s = block_reduce_256(s);
    if (threadIdx.x == 0) g_costsum[b] = s;
}

// per (batch, row-chunk of 256): accumulate u[k] = sum_r w_r * P[r][k], SW, SWPN
__global__ __launch_bounds__(256) void prep_kernel(const float* __restrict__ P) {
    int b = blockIdx.y, s = blockIdx.x, t = threadIdx.x;
    int bN = b * NN;
    float inv = 1.f / (g_costsum[b] + EPSF);
    int r0 = s * 256;
    float u = 0.f;
#pragma unroll 4
    for (int rr = 0; rr < 256; ++rr) {
        int r = bN + r0 + rr;
        float w = g_curr[r] * inv;
        u += w * P[(size_t)r * DD + t];
    }
    atomicAdd(&g_u[b * DD + t], u);
    // one row per thread for SW / SWPN
    int r = bN + r0 + t;
    float w = g_curr[r] * inv;
    float sw = block_reduce_256(w);
    __syncthreads();
    float swpn = block_reduce_256(w * g_pn[r]);
    if (t == 0) {
        atomicAdd(&g_SW[b], sw);
        atomicAdd(&g_SWPN[b], swpn);
    }
}

// warp per column: result += cost_c * bw_c * (SWPN + SW*ln_c - 2*<u, l_c>)
__global__ __launch_bounds__(256) void final_kernel(const float* __restrict__ L,
                                                    float* out) {
    int blk = blockIdx.x;
    int b = blk >> 8;
    int c0 = (blk & 255) * 8;
    int bN = b * NN;
    __shared__ float su[DD];
    su[threadIdx.x] = g_u[b * DD + threadIdx.x];
    __syncthreads();
    int wid = threadIdx.x >> 5, lane = threadIdx.x & 31;
    int c = c0 + wid;
    const float4* lrow = (const float4*)(L + ((size_t)bN + c) * DD);
    const float4* urow = (const float4*)su;
    float4 l0 = lrow[lane * 2], l1 = lrow[lane * 2 + 1];
    float4 u0 = urow[lane * 2], u1 = urow[lane * 2 + 1];
    float d = u0.x * l0.x + u0.y * l0.y + u0.z * l0.z + u0.w * l0.w +
              u1.x * l1.x + u1.y * l1.y + u1.z * l1.z + u1.w * l1.w;
#pragma unroll
    for (int o = 16; o; o >>= 1) d += __shfl_down_sync(0xffffffffu, d, o);
    __shared__ float rr[8];
    if (lane == 0) {
        float SW = g_SW[b], SWPN = g_SWPN[b];
        float colsum = SWPN + SW * g_ln[bN + c] - 2.f * d;
        float co = g_cost[bN + c];
        float bw = fminf(co / (co * SW + EPSF), 1.f);
        rr[wid] = co * bw * colsum;
    }
    __syncthreads();
    if (threadIdx.x == 0) {
        float t = 0.f;
#pragma unroll
        for (int i = 0; i < 8; ++i) t += rr[i];
        atomicAdd(out, t);
    }
}

// ---------------- launch ----------------------------------------------------
extern "C" void kernel_launch(void* const* d_in, const int* in_sizes, int n_in,
                              void* d_out, int out_size) {
    const float* preds = (const float*)d_in[0];
    const float* labels = (const float*)d_in[1];
    float* out = (float*)d_out;

    cudaFuncSetAttribute(minpw_kernel, cudaFuncAttributeMaxDynamicSharedMemorySize, SMEM_MM);

    init_kernel<<<(BB * NN + 255) / 256, 256>>>(out);
    split_norms_kernel<<<(2 * BB * NN) / 8, 256>>>(preds, labels);
    minpw_kernel<<<dim3(NN / 128, NN / 128, BB), 256, SMEM_MM>>>();
    compact_kernel<<<(BB * NN) / 256, 256>>>();
    rare_kernel<<<1, 1024>>>(preds, labels, out);
    costsum_kernel<<<BB, 256>>>();
    prep_kernel<<<dim3(NN / 256, BB), 256>>>(preds);
    final_kernel<<<BB * (NN / 8), 256>>>(labels, out);
}